// round 11
// baseline (speedup 1.0000x reference)
#include <cuda_runtime.h>
#include <cuda_bf16.h>
#include <cstdint>
#include <cfloat>

#define N_ROWS 65536
#define DIM    1024
#define KCB    8192

#define WINDOW   0.30f     // candidate window (~7 sigma of pairwise 1-pass noise)
#define TAU3     2.0e-3f   // full-refine fp32->fp64 shortlist window
#define WLC_CAP  32768
#define WLF_CAP  1024
#define MAX_CAND 64

#define BM 128
#define BN 128
#define KC 64
#define N_TILES (KCB / BN)                        // 64
#define CHUNKS_PER_TILE (DIM / KC)                // 16
#define TOTAL_CHUNKS (N_TILES * CHUNKS_PER_TILE)  // 1024
#define GEMM_THREADS 256

// ---- hmma1 SMEM layout: 2 stages + epilogue scratch + running top-6 ----
#define H1_STAGE   32768
#define H1_A       0
#define H1_B       16384
#define SM_ETV     65536                  // float[128][4][3] = 6144
#define SM_ETI     71680                  // int  [128][4][3] = 6144
#define SM_T6V     77824                  // float[128][6]    = 3072
#define SM_T6I     80896                  // int  [128][6]    = 3072
#define H1_SMEM    83968

// ---- scratch (__device__ globals; allocation-free rule) ----
__device__ __nv_bfloat16 g_zh[(size_t)N_ROWS * DIM];   // 128 MB
__device__ __nv_bfloat16 g_cbh[(size_t)KCB * DIM];     // 16 MB
__device__ float         g_cbT[(size_t)KCB * DIM];     // 32 MB
__device__ float g_t6v[(size_t)N_ROWS * 6];            // per-row top-6 values
__device__ int   g_t6i[(size_t)N_ROWS * 6];            // per-row top-6 indices
__device__ int   g_argmin[N_ROWS];
__device__ int   g_wlc[WLC_CAP];
__device__ int   g_wlc_count;
__device__ int   g_wlf[WLF_CAP];
__device__ int   g_wlf_count;

// ============================ helpers ============================
__device__ __forceinline__ uint32_t smem_to_u32(const void* p) {
    uint32_t a;
    asm("{ .reg .u64 t; cvta.to.shared.u64 t, %1; cvt.u32.u64 %0, t; }" : "=r"(a) : "l"(p));
    return a;
}
#define SWZ128(o) ((o) ^ (((o) >> 3) & 0x70))

#define CP_ASYNC16(sm, g) \
    asm volatile("cp.async.cg.shared.global [%0], [%1], 16;" :: "r"(sm), "l"(g) : "memory")
#define CP_COMMIT()  asm volatile("cp.async.commit_group;" ::: "memory")
#define CP_WAIT1()   asm volatile("cp.async.wait_group 1;" ::: "memory")
#define CP_WAIT0()   asm volatile("cp.async.wait_group 0;" ::: "memory")

#define LDMATRIX_X4(r0, r1, r2, r3, a) \
    asm volatile("ldmatrix.sync.aligned.m8n8.x4.shared.b16 {%0,%1,%2,%3}, [%4];" \
                 : "=r"(r0), "=r"(r1), "=r"(r2), "=r"(r3) : "r"(a))

#define MMA_BF16(c0, c1, c2, c3, a0, a1, a2, a3, b0, b1) \
    asm volatile("mma.sync.aligned.m16n8k16.row.col.f32.bf16.bf16.f32 " \
                 "{%0,%1,%2,%3}, {%4,%5,%6,%7}, {%8,%9}, {%0,%1,%2,%3};" \
                 : "+f"(c0), "+f"(c1), "+f"(c2), "+f"(c3) \
                 : "r"(a0), "r"(a1), "r"(a2), "r"(a3), "r"(b0), "r"(b1))

// sorted-3 insertion with first-index tie-break
#define INS3(v, i) do { \
    if (v < v1 || (v == v1 && (i) < j1)) { v3 = v2; j3 = j2; v2 = v1; j2 = j1; v1 = v; j1 = (i); } \
    else if (v < v2 || (v == v2 && (i) < j2)) { v3 = v2; j3 = j2; v2 = v; j2 = (i); } \
    else if (v < v3 || (v == v3 && (i) < j3)) { v3 = v; j3 = (i); } \
} while (0)

// ---------------------------------------------------------------------------
// Prep 1: transpose codebook -> cbT fp32 + cbh bf16; reset worklists.
// ---------------------------------------------------------------------------
__global__ void vq_prep_cb(const float* __restrict__ cb) {
    if (blockIdx.x == 0 && blockIdx.y == 0 && threadIdx.x == 0 && threadIdx.y == 0) {
        g_wlc_count = 0;
        g_wlf_count = 0;
    }
    __shared__ float tile[32][33];
    const int kBase = blockIdx.x * 32;
    const int dBase = blockIdx.y * 32;
    const int tx = threadIdx.x, ty = threadIdx.y;
#pragma unroll
    for (int i = 0; i < 4; i++)
        tile[ty + i * 8][tx] = cb[(size_t)(dBase + ty + i * 8) * KCB + (kBase + tx)];
    __syncthreads();
#pragma unroll
    for (int i = 0; i < 4; i++) {
        const float v = tile[tx][ty + i * 8];
        const size_t o = (size_t)(kBase + ty + i * 8) * DIM + (dBase + tx);
        g_cbT[o] = v;
        g_cbh[o] = __float2bfloat16(v);
    }
}

// ---------------------------------------------------------------------------
// Prep 2: z -> bf16.
// ---------------------------------------------------------------------------
__global__ void vq_prep_z(const float* __restrict__ z) {
    const size_t total4 = (size_t)N_ROWS * DIM / 4;
    const size_t stride = (size_t)gridDim.x * blockDim.x;
    const float4* z4 = (const float4*)z;
    __nv_bfloat162* h2 = (__nv_bfloat162*)g_zh;
    for (size_t t = (size_t)blockIdx.x * blockDim.x + threadIdx.x; t < total4; t += stride) {
        const float4 v = z4[t];
        h2[t * 2 + 0] = __nv_bfloat162(__float2bfloat16(v.x), __float2bfloat16(v.y));
        h2[t * 2 + 1] = __nv_bfloat162(__float2bfloat16(v.z), __float2bfloat16(v.w));
    }
}

// ---------------------------------------------------------------------------
// hmma1: single-pass bf16 GEMM + fused per-row top-6 candidate tracking.
// ---------------------------------------------------------------------------
__global__ __launch_bounds__(GEMM_THREADS, 2)
void vq_hmma1_kernel() {
    extern __shared__ char smem[];
    const uint32_t sb = smem_to_u32(smem);
    const int tid  = threadIdx.x;
    const int wid  = tid >> 5;
    const int lane = tid & 31;
    const int wm   = wid >> 2;
    const int wn   = wid & 3;
    const int t4   = lane >> 2;
    const int tq   = lane & 3;
    const int rowBase = blockIdx.x * BM;

    float* eTv = (float*)(smem + SM_ETV);
    int*   eTi = (int*)(smem + SM_ETI);
    float* sT6v = (float*)(smem + SM_T6V);
    int*   sT6i = (int*)(smem + SM_T6I);

    // init running top-6
    if (tid < BM) {
#pragma unroll
        for (int j = 0; j < 6; j++) {
            sT6v[tid * 6 + j] = FLT_MAX;
            sT6i[tid * 6 + j] = 0x7FFFFFFF;
        }
    }

    auto load_chunk = [&](int C) {
        const int nt = C >> 4, c = C & 15, s = C & 1;
        const uint32_t stage = sb + s * H1_STAGE;
        const int koff = c * KC;
        const int ntBase = nt * BN;
#pragma unroll
        for (int i = 0; i < 4; i++) {
            const int sg = tid + i * 256;
            const int row = sg >> 3, sc = sg & 7;
            const uint32_t so = SWZ128(row * 128 + sc * 16);
            CP_ASYNC16(stage + H1_A + so, g_zh + (size_t)(rowBase + row) * DIM + koff + sc * 8);
            CP_ASYNC16(stage + H1_B + so, g_cbh + (size_t)(ntBase + row) * DIM + koff + sc * 8);
        }
        CP_COMMIT();
    };

    float acc[4][4][4];

    const int am  = lane >> 3;
    const int ar  = lane & 7;
    const int aRow = ((am & 1) << 3) + ar;
    const int aColB = (am >> 1) << 4;
    const int bRow = ((am >> 1) << 3) + ar;
    const int bColB = (am & 1) << 4;

    load_chunk(0);
    load_chunk(1);

    for (int C = 0; C < TOTAL_CHUNKS; C++) {
        const int s = C & 1, nt = C >> 4, c = C & 15;
        if (C < TOTAL_CHUNKS - 1) { CP_WAIT1(); } else { CP_WAIT0(); }
        __syncthreads();

        if (c == 0) {
#pragma unroll
            for (int mi = 0; mi < 4; mi++)
#pragma unroll
                for (int ni = 0; ni < 4; ni++)
#pragma unroll
                    for (int r = 0; r < 4; r++) acc[mi][ni][r] = 0.0f;
        }

        const uint32_t aB = sb + s * H1_STAGE + H1_A;
        const uint32_t bB = sb + s * H1_STAGE + H1_B;

#pragma unroll
        for (int ks = 0; ks < 4; ks++) {
            const int kb = ks * 32;
            uint32_t af[16], bf[16];
#pragma unroll
            for (int mi = 0; mi < 4; mi++) {
                const int row = wm * 64 + mi * 16 + aRow;
                LDMATRIX_X4(af[mi*4+0], af[mi*4+1], af[mi*4+2], af[mi*4+3],
                            aB + SWZ128(row * 128 + kb + aColB));
            }
#pragma unroll
            for (int np = 0; np < 2; np++) {
                const int nrow = wn * 32 + np * 16 + bRow;
                LDMATRIX_X4(bf[np*8+0], bf[np*8+1], bf[np*8+4], bf[np*8+5],
                            bB + SWZ128(nrow * 128 + kb + bColB));
            }
#pragma unroll
            for (int mi = 0; mi < 4; mi++)
#pragma unroll
                for (int ni = 0; ni < 4; ni++)
                    MMA_BF16(acc[mi][ni][0], acc[mi][ni][1], acc[mi][ni][2], acc[mi][ni][3],
                             af[mi*4+0], af[mi*4+1], af[mi*4+2], af[mi*4+3],
                             bf[ni*4+0], bf[ni*4+1]);
        }
        __syncthreads();

        if (C + 2 < TOTAL_CHUNKS) load_chunk(C + 2);

        // ---- n-tile epilogue: per-row top-3 within tile, fold into top-6 ----
        if (c == 15) {
            const int colBase = nt * BN + wn * 32 + tq * 2;
#pragma unroll
            for (int mi = 0; mi < 4; mi++) {
#pragma unroll
                for (int half = 0; half < 2; half++) {
                    const int row = wm * 64 + mi * 16 + half * 8 + t4;
                    float v1 = FLT_MAX, v2 = FLT_MAX, v3 = FLT_MAX;
                    int   j1 = 0x7FFFFFFF, j2 = 0x7FFFFFFF, j3 = 0x7FFFFFFF;
#pragma unroll
                    for (int ni = 0; ni < 4; ni++)
#pragma unroll
                        for (int cc = 0; cc < 2; cc++) {
                            const float v = acc[mi][ni][half * 2 + cc];
                            const int col = colBase + ni * 8 + cc;
                            INS3(v, col);
                        }
                    // quad merge (lanes tq=0..3 share this row)
#pragma unroll
                    for (int off = 1; off <= 2; off <<= 1) {
                        const float ov1 = __shfl_xor_sync(0xFFFFFFFFu, v1, off);
                        const float ov2 = __shfl_xor_sync(0xFFFFFFFFu, v2, off);
                        const float ov3 = __shfl_xor_sync(0xFFFFFFFFu, v3, off);
                        const int   oj1 = __shfl_xor_sync(0xFFFFFFFFu, j1, off);
                        const int   oj2 = __shfl_xor_sync(0xFFFFFFFFu, j2, off);
                        const int   oj3 = __shfl_xor_sync(0xFFFFFFFFu, j3, off);
                        INS3(ov1, oj1);
                        INS3(ov2, oj2);
                        INS3(ov3, oj3);
                    }
                    if (tq == 0) {
                        eTv[row * 12 + wn * 3 + 0] = v1;
                        eTv[row * 12 + wn * 3 + 1] = v2;
                        eTv[row * 12 + wn * 3 + 2] = v3;
                        eTi[row * 12 + wn * 3 + 0] = j1;
                        eTi[row * 12 + wn * 3 + 1] = j2;
                        eTi[row * 12 + wn * 3 + 2] = j3;
                    }
                }
            }
            __syncthreads();
            if (tid < BM) {
                float t6v[6];
                int   t6i[6];
#pragma unroll
                for (int j = 0; j < 6; j++) {
                    t6v[j] = sT6v[tid * 6 + j];
                    t6i[j] = sT6i[tid * 6 + j];
                }
#pragma unroll
                for (int e = 0; e < 12; e++) {
                    float tv = eTv[tid * 12 + e];
                    int   ti = eTi[tid * 12 + e];
#pragma unroll
                    for (int j = 0; j < 6; j++) {
                        const bool lt = tv < t6v[j] || (tv == t6v[j] && ti < t6i[j]);
                        if (lt) {
                            const float fv = t6v[j]; const int fi = t6i[j];
                            t6v[j] = tv; t6i[j] = ti;
                            tv = fv; ti = fi;
                        }
                    }
                }
#pragma unroll
                for (int j = 0; j < 6; j++) {
                    sT6v[tid * 6 + j] = t6v[j];
                    sT6i[tid * 6 + j] = t6i[j];
                }
            }
            __syncthreads();
        }
    }

    // finalize: argmin = top1; classify rows into candidate / full worklists
    if (tid < BM) {
        const int row = rowBase + tid;
        const float v0 = sT6v[tid * 6 + 0];
        int cwin = 0;
#pragma unroll
        for (int j = 0; j < 6; j++) {
            const float vj = sT6v[tid * 6 + j];
            g_t6v[(size_t)row * 6 + j] = vj;
            g_t6i[(size_t)row * 6 + j] = sT6i[tid * 6 + j];
            cwin += (vj < v0 + WINDOW) ? 1 : 0;
        }
        g_argmin[row] = sT6i[tid * 6 + 0];
        if (cwin >= 6) {
            const int p = atomicAdd(&g_wlf_count, 1);
            if (p < WLF_CAP) g_wlf[p] = row;
        } else if (cwin >= 2) {
            const int p = atomicAdd(&g_wlc_count, 1);
            if (p < WLC_CAP) g_wlc[p] = row;
        }
    }
}

// ---------------------------------------------------------------------------
// refine_cand: exact fp64 rescore of <=6 tracked candidates per flagged row.
// One warp per row.
// ---------------------------------------------------------------------------
__global__ __launch_bounds__(256)
void vq_refine_cand(const float* __restrict__ z) {
    const int cnt  = min(g_wlc_count, WLC_CAP);
    const int lane = threadIdx.x & 31;
    const int wrp  = threadIdx.x >> 5;

    for (int wi = blockIdx.x * 8 + wrp; wi < cnt; wi += gridDim.x * 8) {
        const int row = g_wlc[wi];
        const float v0 = g_t6v[(size_t)row * 6 + 0];
        const float* zr = z + (size_t)row * DIM;

        double bestV = 1e300;
        int    bestI = 0x7FFFFFFF;
#pragma unroll
        for (int j = 0; j < 6; j++) {
            const float vj = g_t6v[(size_t)row * 6 + j];
            if (!(vj < v0 + WINDOW)) continue;
            const int k = g_t6i[(size_t)row * 6 + j];
            const float* cw = g_cbT + (size_t)k * DIM;
            double sd = 0.0;
#pragma unroll 4
            for (int d = lane; d < DIM; d += 32)
                sd += (double)cw[d] * (double)zr[d];
#pragma unroll
            for (int off = 16; off > 0; off >>= 1)
                sd += __shfl_down_sync(0xFFFFFFFFu, sd, off);
            sd = __shfl_sync(0xFFFFFFFFu, sd, 0);
            if (sd < bestV || (sd == bestV && k < bestI)) { bestV = sd; bestI = k; }
        }
        if (lane == 0) g_argmin[row] = bestI;
    }
}

// ---------------------------------------------------------------------------
// refine_full: exact pass (fp32 full rescan -> fp64 finish) for overflow rows.
// ---------------------------------------------------------------------------
__global__ __launch_bounds__(256)
void vq_refine_full(const float* __restrict__ A) {
    __shared__ float  zs[DIM];
    __shared__ float  dots[KCB];
    __shared__ float  red[256];
    __shared__ int    cands[MAX_CAND];
    __shared__ double cval[MAX_CAND];
    __shared__ int    ncand;

    const int tid  = threadIdx.x;
    const int lane = tid & 31;
    const int wrp  = tid >> 5;
    const int cnt  = min(g_wlf_count, WLF_CAP);

    for (int wi = blockIdx.x; wi < cnt; wi += gridDim.x) {
        const int row = g_wlf[wi];
#pragma unroll
        for (int i = 0; i < DIM / 256; i++)
            zs[tid + i * 256] = A[(size_t)row * DIM + tid + i * 256];
        if (tid == 0) ncand = 0;
        __syncthreads();

        const float4* z4 = (const float4*)zs;
        float localMin = FLT_MAX;
        for (int k = tid; k < KCB; k += 256) {
            const float4* c4 = (const float4*)(g_cbT + (size_t)k * DIM);
            float sacc = 0.0f;
#pragma unroll 8
            for (int d = 0; d < DIM / 4; d++) {
                const float4 cc = c4[d];
                const float4 zz = z4[d];
                sacc = fmaf(cc.x, zz.x, sacc);
                sacc = fmaf(cc.y, zz.y, sacc);
                sacc = fmaf(cc.z, zz.z, sacc);
                sacc = fmaf(cc.w, zz.w, sacc);
            }
            dots[k] = sacc;
            localMin = fminf(localMin, sacc);
        }
        red[tid] = localMin;
        __syncthreads();
        for (int off = 128; off > 0; off >>= 1) {
            if (tid < off) red[tid] = fminf(red[tid], red[tid + off]);
            __syncthreads();
        }
        const float bmin = red[0];

        for (int k = tid; k < KCB; k += 256) {
            if (dots[k] < bmin + TAU3) {
                const int p = atomicAdd(&ncand, 1);
                if (p < MAX_CAND) cands[p] = k;
            }
        }
        __syncthreads();
        const int nc = min(ncand, MAX_CAND);

        for (int ci = wrp; ci < nc; ci += 8) {
            const int k = cands[ci];
            const float* cbp = g_cbT + (size_t)k * DIM;
            double sd = 0.0;
            for (int d = lane; d < DIM; d += 32)
                sd += (double)cbp[d] * (double)zs[d];
#pragma unroll
            for (int off = 16; off > 0; off >>= 1)
                sd += __shfl_down_sync(0xFFFFFFFFu, sd, off);
            if (lane == 0) cval[ci] = sd;
        }
        __syncthreads();

        if (tid == 0) {
            double bv = cval[0];
            int    bi = cands[0];
            for (int c2 = 1; c2 < nc; c2++) {
                const double v = cval[c2];
                const int    x = cands[c2];
                if (v < bv || (v == bv && x < bi)) { bv = v; bi = x; }
            }
            g_argmin[row] = bi;
        }
        __syncthreads();
    }
}

// ---------------------------------------------------------------------------
// Gather: out[n][:] = g_cbT[argmin[n]][:]
// ---------------------------------------------------------------------------
__global__ void vq_gather_kernel(float* __restrict__ out) {
    const int n = blockIdx.x;
    const int idx = g_argmin[n];
    const float4* src = (const float4*)(g_cbT + (size_t)idx * DIM);
    float4* dst = (float4*)(out + (size_t)n * DIM);
    dst[threadIdx.x] = src[threadIdx.x];
}

// ---------------------------------------------------------------------------
extern "C" void kernel_launch(void* const* d_in, const int* in_sizes, int n_in,
                              void* d_out, int out_size) {
    const float* z  = (const float*)d_in[0];
    const float* cb = (const float*)d_in[1];
    float* out = (float*)d_out;

    cudaFuncSetAttribute(vq_hmma1_kernel, cudaFuncAttributeMaxDynamicSharedMemorySize, H1_SMEM);

    dim3 tgrid(KCB / 32, DIM / 32);
    dim3 tblk(32, 8);
    vq_prep_cb<<<tgrid, tblk>>>(cb);
    vq_prep_z<<<8192, 256>>>(z);

    vq_hmma1_kernel<<<N_ROWS / BM, GEMM_THREADS, H1_SMEM>>>();

    vq_refine_cand<<<1024, 256>>>(z);
    vq_refine_full<<<64, 256>>>(z);
    vq_gather_kernel<<<N_ROWS, 256>>>(out);
}

// round 12
// speedup vs baseline: 1.4947x; 1.4947x over previous
#include <cuda_runtime.h>
#include <cuda_bf16.h>
#include <cuda_fp16.h>
#include <cstdint>
#include <cfloat>

#define N_ROWS 65536
#define DIM    1024
#define KCB    8192

#define WINDOW   0.40f     // candidate window (fp16 store err + bf16 GEMM noise, >2x margin)
#define TAU3     2.0e-3f   // full-refine fp32->fp64 shortlist window
#define WLC_CAP  32768
#define WLF_CAP  1024
#define CAND_CAP 8
#define MAX_CAND 64

#define BM 128
#define BN 128
#define KC 64
#define N_TILES (KCB / BN)                        // 64
#define CHUNKS_PER_TILE (DIM / KC)                // 16
#define TOTAL_CHUNKS (N_TILES * CHUNKS_PER_TILE)  // 1024
#define GEMM_THREADS 256

// ---- hmma1 SMEM: 2 stages only ----
#define H1_STAGE   32768
#define H1_A       0
#define H1_B       16384
#define H1_SMEM    (2 * H1_STAGE)                 // 65536

// ---- scratch (__device__ globals; allocation-free rule) ----
__device__ __nv_bfloat16 g_zh[(size_t)N_ROWS * DIM];   // 128 MB
__device__ __nv_bfloat16 g_cbh[(size_t)KCB * DIM];     // 16 MB
__device__ float         g_cbT[(size_t)KCB * DIM];     // 32 MB
__device__ __half        g_dots[(size_t)N_ROWS * KCB]; // 1 GB dot matrix (fp16)
__device__ int   g_cand[(size_t)N_ROWS * CAND_CAP];    // per-row candidates
__device__ int   g_ccnt[N_ROWS];
__device__ int   g_argmin[N_ROWS];
__device__ int   g_wlc[WLC_CAP];
__device__ int   g_wlc_count;
__device__ int   g_wlf[WLF_CAP];
__device__ int   g_wlf_count;

// ============================ helpers ============================
__device__ __forceinline__ uint32_t smem_to_u32(const void* p) {
    uint32_t a;
    asm("{ .reg .u64 t; cvta.to.shared.u64 t, %1; cvt.u32.u64 %0, t; }" : "=r"(a) : "l"(p));
    return a;
}
#define SWZ128(o) ((o) ^ (((o) >> 3) & 0x70))

#define CP_ASYNC16(sm, g) \
    asm volatile("cp.async.cg.shared.global [%0], [%1], 16;" :: "r"(sm), "l"(g) : "memory")
#define CP_COMMIT()  asm volatile("cp.async.commit_group;" ::: "memory")
#define CP_WAIT1()   asm volatile("cp.async.wait_group 1;" ::: "memory")
#define CP_WAIT0()   asm volatile("cp.async.wait_group 0;" ::: "memory")

#define LDMATRIX_X4(r0, r1, r2, r3, a) \
    asm volatile("ldmatrix.sync.aligned.m8n8.x4.shared.b16 {%0,%1,%2,%3}, [%4];" \
                 : "=r"(r0), "=r"(r1), "=r"(r2), "=r"(r3) : "r"(a))

#define MMA_BF16(c0, c1, c2, c3, a0, a1, a2, a3, b0, b1) \
    asm volatile("mma.sync.aligned.m16n8k16.row.col.f32.bf16.bf16.f32 " \
                 "{%0,%1,%2,%3}, {%4,%5,%6,%7}, {%8,%9}, {%0,%1,%2,%3};" \
                 : "+f"(c0), "+f"(c1), "+f"(c2), "+f"(c3) \
                 : "r"(a0), "r"(a1), "r"(a2), "r"(a3), "r"(b0), "r"(b1))

// ---------------------------------------------------------------------------
// Prep 1: transpose codebook -> cbT fp32 + cbh bf16; reset worklists.
// ---------------------------------------------------------------------------
__global__ void vq_prep_cb(const float* __restrict__ cb) {
    if (blockIdx.x == 0 && blockIdx.y == 0 && threadIdx.x == 0 && threadIdx.y == 0) {
        g_wlc_count = 0;
        g_wlf_count = 0;
    }
    __shared__ float tile[32][33];
    const int kBase = blockIdx.x * 32;
    const int dBase = blockIdx.y * 32;
    const int tx = threadIdx.x, ty = threadIdx.y;
#pragma unroll
    for (int i = 0; i < 4; i++)
        tile[ty + i * 8][tx] = cb[(size_t)(dBase + ty + i * 8) * KCB + (kBase + tx)];
    __syncthreads();
#pragma unroll
    for (int i = 0; i < 4; i++) {
        const float v = tile[tx][ty + i * 8];
        const size_t o = (size_t)(kBase + ty + i * 8) * DIM + (dBase + tx);
        g_cbT[o] = v;
        g_cbh[o] = __float2bfloat16(v);
    }
}

// ---------------------------------------------------------------------------
// Prep 2: z -> bf16.
// ---------------------------------------------------------------------------
__global__ void vq_prep_z(const float* __restrict__ z) {
    const size_t total4 = (size_t)N_ROWS * DIM / 4;
    const size_t stride = (size_t)gridDim.x * blockDim.x;
    const float4* z4 = (const float4*)z;
    __nv_bfloat162* h2 = (__nv_bfloat162*)g_zh;
    for (size_t t = (size_t)blockIdx.x * blockDim.x + threadIdx.x; t < total4; t += stride) {
        const float4 v = z4[t];
        h2[t * 2 + 0] = __nv_bfloat162(__float2bfloat16(v.x), __float2bfloat16(v.y));
        h2[t * 2 + 1] = __nv_bfloat162(__float2bfloat16(v.z), __float2bfloat16(v.w));
    }
}

// ---------------------------------------------------------------------------
// hmma1: single-pass bf16 GEMM; epilogue = store D tile as fp16 (no reductions).
// ---------------------------------------------------------------------------
__global__ __launch_bounds__(GEMM_THREADS, 2)
void vq_hmma1_kernel() {
    extern __shared__ char smem[];
    const uint32_t sb = smem_to_u32(smem);
    const int tid  = threadIdx.x;
    const int lane = tid & 31;
    const int wid  = tid >> 5;
    const int wm   = wid >> 2;
    const int wn   = wid & 3;
    const int t4   = lane >> 2;
    const int tq   = lane & 3;
    const int rowBase = blockIdx.x * BM;

    auto load_chunk = [&](int C) {
        const int nt = C >> 4, c = C & 15, s = C & 1;
        const uint32_t stage = sb + s * H1_STAGE;
        const int koff = c * KC;
        const int ntBase = nt * BN;
#pragma unroll
        for (int i = 0; i < 4; i++) {
            const int sg = tid + i * 256;
            const int row = sg >> 3, sc = sg & 7;
            const uint32_t so = SWZ128(row * 128 + sc * 16);
            CP_ASYNC16(stage + H1_A + so, g_zh + (size_t)(rowBase + row) * DIM + koff + sc * 8);
            CP_ASYNC16(stage + H1_B + so, g_cbh + (size_t)(ntBase + row) * DIM + koff + sc * 8);
        }
        CP_COMMIT();
    };

    float acc[4][4][4];

    const int am  = lane >> 3;
    const int ar  = lane & 7;
    const int aRow = ((am & 1) << 3) + ar;
    const int aColB = (am >> 1) << 4;
    const int bRow = ((am >> 1) << 3) + ar;
    const int bColB = (am & 1) << 4;

    load_chunk(0);
    load_chunk(1);

    for (int C = 0; C < TOTAL_CHUNKS; C++) {
        const int s = C & 1, nt = C >> 4, c = C & 15;
        if (C < TOTAL_CHUNKS - 1) { CP_WAIT1(); } else { CP_WAIT0(); }
        __syncthreads();

        if (c == 0) {
#pragma unroll
            for (int mi = 0; mi < 4; mi++)
#pragma unroll
                for (int ni = 0; ni < 4; ni++)
#pragma unroll
                    for (int r = 0; r < 4; r++) acc[mi][ni][r] = 0.0f;
        }

        const uint32_t aB = sb + s * H1_STAGE + H1_A;
        const uint32_t bB = sb + s * H1_STAGE + H1_B;

#pragma unroll
        for (int ks = 0; ks < 4; ks++) {
            const int kb = ks * 32;
            uint32_t af[16], bf[16];
#pragma unroll
            for (int mi = 0; mi < 4; mi++) {
                const int row = wm * 64 + mi * 16 + aRow;
                LDMATRIX_X4(af[mi*4+0], af[mi*4+1], af[mi*4+2], af[mi*4+3],
                            aB + SWZ128(row * 128 + kb + aColB));
            }
#pragma unroll
            for (int np = 0; np < 2; np++) {
                const int nrow = wn * 32 + np * 16 + bRow;
                LDMATRIX_X4(bf[np*8+0], bf[np*8+1], bf[np*8+4], bf[np*8+5],
                            bB + SWZ128(nrow * 128 + kb + bColB));
            }
#pragma unroll
            for (int mi = 0; mi < 4; mi++)
#pragma unroll
                for (int ni = 0; ni < 4; ni++)
                    MMA_BF16(acc[mi][ni][0], acc[mi][ni][1], acc[mi][ni][2], acc[mi][ni][3],
                             af[mi*4+0], af[mi*4+1], af[mi*4+2], af[mi*4+3],
                             bf[ni*4+0], bf[ni*4+1]);
        }
        __syncthreads();

        if (C + 2 < TOTAL_CHUNKS) load_chunk(C + 2);

        // ---- epilogue: dump D tile as fp16 ----
        if (c == 15) {
            const int colBase = nt * BN + wn * 32 + tq * 2;
#pragma unroll
            for (int mi = 0; mi < 4; mi++) {
#pragma unroll
                for (int half = 0; half < 2; half++) {
                    const int row = rowBase + wm * 64 + mi * 16 + half * 8 + t4;
                    __half2* dst = (__half2*)(g_dots + (size_t)row * KCB);
#pragma unroll
                    for (int ni = 0; ni < 4; ni++) {
                        const int col = colBase + ni * 8;
                        dst[col >> 1] = __floats2half2_rn(acc[mi][ni][half * 2 + 0],
                                                          acc[mi][ni][half * 2 + 1]);
                    }
                }
            }
        }
    }
}

// ---------------------------------------------------------------------------
// scan: warp per row. Pass1: min+argmin (tie-break). Pass2 (L1-resident):
// collect candidates within WINDOW; classify row.
// ---------------------------------------------------------------------------
__global__ __launch_bounds__(256)
void vq_scan_kernel() {
    __shared__ int scnt[8];
    const int w    = threadIdx.x >> 5;
    const int lane = threadIdx.x & 31;
    const int row  = blockIdx.x * 8 + w;
    const __half2* dp = (const __half2*)(g_dots + (size_t)row * KCB);

    float minv = FLT_MAX;
    int   mink = 0x7FFFFFFF;
#pragma unroll 4
    for (int i = lane; i < KCB / 2; i += 32) {
        const __half2 h = dp[i];
        const float v0 = __low2float(h), v1 = __high2float(h);
        const int k0 = i * 2, k1 = i * 2 + 1;
        if (v0 < minv || (v0 == minv && k0 < mink)) { minv = v0; mink = k0; }
        if (v1 < minv || (v1 == minv && k1 < mink)) { minv = v1; mink = k1; }
    }
#pragma unroll
    for (int off = 16; off > 0; off >>= 1) {
        const float ov = __shfl_xor_sync(0xFFFFFFFFu, minv, off);
        const int   ok = __shfl_xor_sync(0xFFFFFFFFu, mink, off);
        if (ov < minv || (ov == minv && ok < mink)) { minv = ov; mink = ok; }
    }

    if (lane == 0) scnt[w] = 0;
    __syncwarp();

    const float thr = minv + WINDOW;
#pragma unroll 4
    for (int i = lane; i < KCB / 2; i += 32) {
        const __half2 h = dp[i];
        const float v0 = __low2float(h), v1 = __high2float(h);
        if (v0 < thr) {
            const int p = atomicAdd(&scnt[w], 1);
            if (p < CAND_CAP) g_cand[(size_t)row * CAND_CAP + p] = i * 2;
        }
        if (v1 < thr) {
            const int p = atomicAdd(&scnt[w], 1);
            if (p < CAND_CAP) g_cand[(size_t)row * CAND_CAP + p] = i * 2 + 1;
        }
    }
    __syncwarp();

    if (lane == 0) {
        const int total = scnt[w];
        g_ccnt[row] = total;
        g_argmin[row] = mink;
        if (total > CAND_CAP) {
            const int p = atomicAdd(&g_wlf_count, 1);
            if (p < WLF_CAP) g_wlf[p] = row;
        } else if (total >= 2) {
            const int p = atomicAdd(&g_wlc_count, 1);
            if (p < WLC_CAP) g_wlc[p] = row;
        }
    }
}

// ---------------------------------------------------------------------------
// refine_cand: exact fp64 rescore of tracked candidates. One warp per row.
// ---------------------------------------------------------------------------
__global__ __launch_bounds__(256)
void vq_refine_cand(const float* __restrict__ z) {
    const int cnt  = min(g_wlc_count, WLC_CAP);
    const int lane = threadIdx.x & 31;
    const int wrp  = threadIdx.x >> 5;

    for (int wi = blockIdx.x * 8 + wrp; wi < cnt; wi += gridDim.x * 8) {
        const int row = g_wlc[wi];
        const int nc = min(g_ccnt[row], CAND_CAP);
        const float* zr = z + (size_t)row * DIM;

        double bestV = 1e300;
        int    bestI = 0x7FFFFFFF;
        for (int j = 0; j < nc; j++) {
            const int k = g_cand[(size_t)row * CAND_CAP + j];
            const float* cw = g_cbT + (size_t)k * DIM;
            double sd = 0.0;
#pragma unroll 4
            for (int d = lane; d < DIM; d += 32)
                sd += (double)cw[d] * (double)zr[d];
#pragma unroll
            for (int off = 16; off > 0; off >>= 1)
                sd += __shfl_down_sync(0xFFFFFFFFu, sd, off);
            sd = __shfl_sync(0xFFFFFFFFu, sd, 0);
            if (sd < bestV || (sd == bestV && k < bestI)) { bestV = sd; bestI = k; }
        }
        if (lane == 0) g_argmin[row] = bestI;
    }
}

// ---------------------------------------------------------------------------
// refine_full: exact pass (fp32 full rescan -> fp64 finish) for overflow rows.
// ---------------------------------------------------------------------------
__global__ __launch_bounds__(256)
void vq_refine_full(const float* __restrict__ A) {
    __shared__ float  zs[DIM];
    __shared__ float  dots[KCB];
    __shared__ float  red[256];
    __shared__ int    cands[MAX_CAND];
    __shared__ double cval[MAX_CAND];
    __shared__ int    ncand;

    const int tid  = threadIdx.x;
    const int lane = tid & 31;
    const int wrp  = tid >> 5;
    const int cnt  = min(g_wlf_count, WLF_CAP);

    for (int wi = blockIdx.x; wi < cnt; wi += gridDim.x) {
        const int row = g_wlf[wi];
#pragma unroll
        for (int i = 0; i < DIM / 256; i++)
            zs[tid + i * 256] = A[(size_t)row * DIM + tid + i * 256];
        if (tid == 0) ncand = 0;
        __syncthreads();

        const float4* z4 = (const float4*)zs;
        float localMin = FLT_MAX;
        for (int k = tid; k < KCB; k += 256) {
            const float4* c4 = (const float4*)(g_cbT + (size_t)k * DIM);
            float sacc = 0.0f;
#pragma unroll 8
            for (int d = 0; d < DIM / 4; d++) {
                const float4 cc = c4[d];
                const float4 zz = z4[d];
                sacc = fmaf(cc.x, zz.x, sacc);
                sacc = fmaf(cc.y, zz.y, sacc);
                sacc = fmaf(cc.z, zz.z, sacc);
                sacc = fmaf(cc.w, zz.w, sacc);
            }
            dots[k] = sacc;
            localMin = fminf(localMin, sacc);
        }
        red[tid] = localMin;
        __syncthreads();
        for (int off = 128; off > 0; off >>= 1) {
            if (tid < off) red[tid] = fminf(red[tid], red[tid + off]);
            __syncthreads();
        }
        const float bmin = red[0];

        for (int k = tid; k < KCB; k += 256) {
            if (dots[k] < bmin + TAU3) {
                const int p = atomicAdd(&ncand, 1);
                if (p < MAX_CAND) cands[p] = k;
            }
        }
        __syncthreads();
        const int nc = min(ncand, MAX_CAND);

        for (int ci = wrp; ci < nc; ci += 8) {
            const int k = cands[ci];
            const float* cbp = g_cbT + (size_t)k * DIM;
            double sd = 0.0;
            for (int d = lane; d < DIM; d += 32)
                sd += (double)cbp[d] * (double)zs[d];
#pragma unroll
            for (int off = 16; off > 0; off >>= 1)
                sd += __shfl_down_sync(0xFFFFFFFFu, sd, off);
            if (lane == 0) cval[ci] = sd;
        }
        __syncthreads();

        if (tid == 0) {
            double bv = cval[0];
            int    bi = cands[0];
            for (int c2 = 1; c2 < nc; c2++) {
                const double v = cval[c2];
                const int    x = cands[c2];
                if (v < bv || (v == bv && x < bi)) { bv = v; bi = x; }
            }
            g_argmin[row] = bi;
        }
        __syncthreads();
    }
}

// ---------------------------------------------------------------------------
// Gather: out[n][:] = g_cbT[argmin[n]][:]
// ---------------------------------------------------------------------------
__global__ void vq_gather_kernel(float* __restrict__ out) {
    const int n = blockIdx.x;
    const int idx = g_argmin[n];
    const float4* src = (const float4*)(g_cbT + (size_t)idx * DIM);
    float4* dst = (float4*)(out + (size_t)n * DIM);
    dst[threadIdx.x] = src[threadIdx.x];
}

// ---------------------------------------------------------------------------
extern "C" void kernel_launch(void* const* d_in, const int* in_sizes, int n_in,
                              void* d_out, int out_size) {
    const float* z  = (const float*)d_in[0];
    const float* cb = (const float*)d_in[1];
    float* out = (float*)d_out;

    cudaFuncSetAttribute(vq_hmma1_kernel, cudaFuncAttributeMaxDynamicSharedMemorySize, H1_SMEM);

    dim3 tgrid(KCB / 32, DIM / 32);
    dim3 tblk(32, 8);
    vq_prep_cb<<<tgrid, tblk>>>(cb);
    vq_prep_z<<<8192, 256>>>(z);

    vq_hmma1_kernel<<<N_ROWS / BM, GEMM_THREADS, H1_SMEM>>>();

    vq_scan_kernel<<<N_ROWS / 8, 256>>>();
    vq_refine_cand<<<2048, 256>>>(z);
    vq_refine_full<<<64, 256>>>(z);
    vq_gather_kernel<<<N_ROWS, 256>>>(out);
}

// round 14
// speedup vs baseline: 1.6120x; 1.0785x over previous
#include <cuda_runtime.h>
#include <cuda_bf16.h>
#include <cuda_fp16.h>
#include <cstdint>
#include <cfloat>

#define N_ROWS 65536
#define DIM    1024
#define KCB    8192

#define WINDOW   0.40f     // candidate window (fp16 store err + bf16 GEMM noise, >2x margin)
#define TAU3     2.0e-3f   // full-refine fp32->fp64 shortlist window
#define WLC_CAP  32768
#define WLF_CAP  1024
#define CAND_CAP 8
#define MAX_CAND 64

#define BM 128
#define BN 128
#define KC 64
#define N_TILES (KCB / BN)                        // 64
#define CHUNKS_PER_TILE (DIM / KC)                // 16
#define TOTAL_CHUNKS (N_TILES * CHUNKS_PER_TILE)  // 1024
#define GEMM_THREADS 256

// row = 8192 halves = 16384 bytes = 1024 x uint4
#define ROW_U4 1024

// ---- hmma1 SMEM: 2 stages only ----
#define H1_STAGE   32768
#define H1_A       0
#define H1_B       16384
#define H1_SMEM    (2 * H1_STAGE)                 // 65536

// ---- scratch (__device__ globals; allocation-free rule) ----
__device__ __nv_bfloat16 g_zh[(size_t)N_ROWS * DIM];   // 128 MB
__device__ __nv_bfloat16 g_cbh[(size_t)KCB * DIM];     // 16 MB
__device__ float         g_cbT[(size_t)KCB * DIM];     // 32 MB
__device__ __half        g_dots[(size_t)N_ROWS * KCB]; // 1 GB dot matrix (fp16)
__device__ int   g_cand[(size_t)N_ROWS * CAND_CAP];    // per-row candidates
__device__ int   g_ccnt[N_ROWS];
__device__ int   g_argmin[N_ROWS];
__device__ int   g_wlc[WLC_CAP];
__device__ int   g_wlc_count;
__device__ int   g_wlf[WLF_CAP];
__device__ int   g_wlf_count;

// ============================ helpers ============================
__device__ __forceinline__ uint32_t smem_to_u32(const void* p) {
    uint32_t a;
    asm("{ .reg .u64 t; cvta.to.shared.u64 t, %1; cvt.u32.u64 %0, t; }" : "=r"(a) : "l"(p));
    return a;
}
#define SWZ128(o) ((o) ^ (((o) >> 3) & 0x70))

#define CP_ASYNC16(sm, g) \
    asm volatile("cp.async.cg.shared.global [%0], [%1], 16;" :: "r"(sm), "l"(g) : "memory")
#define CP_COMMIT()  asm volatile("cp.async.commit_group;" ::: "memory")
#define CP_WAIT1()   asm volatile("cp.async.wait_group 1;" ::: "memory")
#define CP_WAIT0()   asm volatile("cp.async.wait_group 0;" ::: "memory")

#define LDMATRIX_X4(r0, r1, r2, r3, a) \
    asm volatile("ldmatrix.sync.aligned.m8n8.x4.shared.b16 {%0,%1,%2,%3}, [%4];" \
                 : "=r"(r0), "=r"(r1), "=r"(r2), "=r"(r3) : "r"(a))

#define MMA_BF16(c0, c1, c2, c3, a0, a1, a2, a3, b0, b1) \
    asm volatile("mma.sync.aligned.m16n8k16.row.col.f32.bf16.bf16.f32 " \
                 "{%0,%1,%2,%3}, {%4,%5,%6,%7}, {%8,%9}, {%0,%1,%2,%3};" \
                 : "+f"(c0), "+f"(c1), "+f"(c2), "+f"(c3) \
                 : "r"(a0), "r"(a1), "r"(a2), "r"(a3), "r"(b0), "r"(b1))

// ---------------------------------------------------------------------------
// Prep 1: transpose codebook -> cbT fp32 + cbh bf16; reset worklists.
// ---------------------------------------------------------------------------
__global__ void vq_prep_cb(const float* __restrict__ cb) {
    if (blockIdx.x == 0 && blockIdx.y == 0 && threadIdx.x == 0 && threadIdx.y == 0) {
        g_wlc_count = 0;
        g_wlf_count = 0;
    }
    __shared__ float tile[32][33];
    const int kBase = blockIdx.x * 32;
    const int dBase = blockIdx.y * 32;
    const int tx = threadIdx.x, ty = threadIdx.y;
#pragma unroll
    for (int i = 0; i < 4; i++)
        tile[ty + i * 8][tx] = cb[(size_t)(dBase + ty + i * 8) * KCB + (kBase + tx)];
    __syncthreads();
#pragma unroll
    for (int i = 0; i < 4; i++) {
        const float v = tile[tx][ty + i * 8];
        const size_t o = (size_t)(kBase + ty + i * 8) * DIM + (dBase + tx);
        g_cbT[o] = v;
        g_cbh[o] = __float2bfloat16(v);
    }
}

// ---------------------------------------------------------------------------
// Prep 2: z -> bf16.
// ---------------------------------------------------------------------------
__global__ void vq_prep_z(const float* __restrict__ z) {
    const size_t total4 = (size_t)N_ROWS * DIM / 4;
    const size_t stride = (size_t)gridDim.x * blockDim.x;
    const float4* z4 = (const float4*)z;
    __nv_bfloat162* h2 = (__nv_bfloat162*)g_zh;
    for (size_t t = (size_t)blockIdx.x * blockDim.x + threadIdx.x; t < total4; t += stride) {
        const float4 v = z4[t];
        h2[t * 2 + 0] = __nv_bfloat162(__float2bfloat16(v.x), __float2bfloat16(v.y));
        h2[t * 2 + 1] = __nv_bfloat162(__float2bfloat16(v.z), __float2bfloat16(v.w));
    }
}

// ---------------------------------------------------------------------------
// hmma1: single-pass bf16 GEMM; epilogue = store D tile as fp16 (no reductions).
// ---------------------------------------------------------------------------
__global__ __launch_bounds__(GEMM_THREADS, 2)
void vq_hmma1_kernel() {
    extern __shared__ char smem[];
    const uint32_t sb = smem_to_u32(smem);
    const int tid  = threadIdx.x;
    const int lane = tid & 31;
    const int wid  = tid >> 5;
    const int wm   = wid >> 2;
    const int wn   = wid & 3;
    const int t4   = lane >> 2;
    const int tq   = lane & 3;
    const int rowBase = blockIdx.x * BM;

    auto load_chunk = [&](int C) {
        const int nt = C >> 4, c = C & 15, s = C & 1;
        const uint32_t stage = sb + s * H1_STAGE;
        const int koff = c * KC;
        const int ntBase = nt * BN;
#pragma unroll
        for (int i = 0; i < 4; i++) {
            const int sg = tid + i * 256;
            const int row = sg >> 3, sc = sg & 7;
            const uint32_t so = SWZ128(row * 128 + sc * 16);
            CP_ASYNC16(stage + H1_A + so, g_zh + (size_t)(rowBase + row) * DIM + koff + sc * 8);
            CP_ASYNC16(stage + H1_B + so, g_cbh + (size_t)(ntBase + row) * DIM + koff + sc * 8);
        }
        CP_COMMIT();
    };

    float acc[4][4][4];

    const int am  = lane >> 3;
    const int ar  = lane & 7;
    const int aRow = ((am & 1) << 3) + ar;
    const int aColB = (am >> 1) << 4;
    const int bRow = ((am >> 1) << 3) + ar;
    const int bColB = (am & 1) << 4;

    load_chunk(0);
    load_chunk(1);

    for (int C = 0; C < TOTAL_CHUNKS; C++) {
        const int s = C & 1, nt = C >> 4, c = C & 15;
        if (C < TOTAL_CHUNKS - 1) { CP_WAIT1(); } else { CP_WAIT0(); }
        __syncthreads();

        if (c == 0) {
#pragma unroll
            for (int mi = 0; mi < 4; mi++)
#pragma unroll
                for (int ni = 0; ni < 4; ni++)
#pragma unroll
                    for (int r = 0; r < 4; r++) acc[mi][ni][r] = 0.0f;
        }

        const uint32_t aB = sb + s * H1_STAGE + H1_A;
        const uint32_t bB = sb + s * H1_STAGE + H1_B;

#pragma unroll
        for (int ks = 0; ks < 4; ks++) {
            const int kb = ks * 32;
            uint32_t af[16], bf[16];
#pragma unroll
            for (int mi = 0; mi < 4; mi++) {
                const int row = wm * 64 + mi * 16 + aRow;
                LDMATRIX_X4(af[mi*4+0], af[mi*4+1], af[mi*4+2], af[mi*4+3],
                            aB + SWZ128(row * 128 + kb + aColB));
            }
#pragma unroll
            for (int np = 0; np < 2; np++) {
                const int nrow = wn * 32 + np * 16 + bRow;
                LDMATRIX_X4(bf[np*8+0], bf[np*8+1], bf[np*8+4], bf[np*8+5],
                            bB + SWZ128(nrow * 128 + kb + bColB));
            }
#pragma unroll
            for (int mi = 0; mi < 4; mi++)
#pragma unroll
                for (int ni = 0; ni < 4; ni++)
                    MMA_BF16(acc[mi][ni][0], acc[mi][ni][1], acc[mi][ni][2], acc[mi][ni][3],
                             af[mi*4+0], af[mi*4+1], af[mi*4+2], af[mi*4+3],
                             bf[ni*4+0], bf[ni*4+1]);
        }
        __syncthreads();

        if (C + 2 < TOTAL_CHUNKS) load_chunk(C + 2);

        // ---- epilogue: dump D tile as fp16 ----
        if (c == 15) {
            const int colBase = nt * BN + wn * 32 + tq * 2;
#pragma unroll
            for (int mi = 0; mi < 4; mi++) {
#pragma unroll
                for (int half = 0; half < 2; half++) {
                    const int row = rowBase + wm * 64 + mi * 16 + half * 8 + t4;
                    __half2* dst = (__half2*)(g_dots + (size_t)row * KCB);
#pragma unroll
                    for (int ni = 0; ni < 4; ni++) {
                        const int col = colBase + ni * 8;
                        dst[col >> 1] = __floats2half2_rn(acc[mi][ni][half * 2 + 0],
                                                          acc[mi][ni][half * 2 + 1]);
                    }
                }
            }
        }
    }
}

// ---------------------------------------------------------------------------
// scan: warp per row over ROW_U4 = 1024 uint4 groups (8 halves each).
// Pass 1: pure hmin2 tournament (value-only min, no index).
// Pass 2 (L1-resident): min8-vs-thr per 16B; unpack only on rare hit.
// count==1 -> argmin directly; 2..8 -> wlc; >8 -> wlf.
// ---------------------------------------------------------------------------
__global__ __launch_bounds__(256)
void vq_scan_kernel() {
    __shared__ int scnt[8];
    const int w    = threadIdx.x >> 5;
    const int lane = threadIdx.x & 31;
    const int row  = blockIdx.x * 8 + w;
    const uint4* dp = (const uint4*)(g_dots + (size_t)row * KCB);  // ROW_U4 x 16B

    // ---- pass 1: vectorized min ----
    __half2 m2 = __float2half2_rn(6.0e4f);
#pragma unroll 4
    for (int i = lane; i < ROW_U4; i += 32) {
        const uint4 u = dp[i];
        const __half2 h0 = *(const __half2*)&u.x;
        const __half2 h1 = *(const __half2*)&u.y;
        const __half2 h2 = *(const __half2*)&u.z;
        const __half2 h3 = *(const __half2*)&u.w;
        m2 = __hmin2(m2, __hmin2(__hmin2(h0, h1), __hmin2(h2, h3)));
    }
    float minv = fminf(__low2float(m2), __high2float(m2));
#pragma unroll
    for (int off = 16; off > 0; off >>= 1)
        minv = fminf(minv, __shfl_xor_sync(0xFFFFFFFFu, minv, off));

    if (lane == 0) scnt[w] = 0;
    __syncwarp();

    // ---- pass 2: threshold collect (L1-resident re-read) ----
    const float thr = minv + WINDOW;
#pragma unroll 4
    for (int i = lane; i < ROW_U4; i += 32) {
        const uint4 u = dp[i];
        const __half2 h0 = *(const __half2*)&u.x;
        const __half2 h1 = *(const __half2*)&u.y;
        const __half2 h2 = *(const __half2*)&u.z;
        const __half2 h3 = *(const __half2*)&u.w;
        const __half2 g2 = __hmin2(__hmin2(h0, h1), __hmin2(h2, h3));
        const float g = fminf(__low2float(g2), __high2float(g2));
        if (g < thr) {
            const __half2 hs[4] = { h0, h1, h2, h3 };
#pragma unroll
            for (int q = 0; q < 4; q++) {
                const float v0 = __low2float(hs[q]), v1 = __high2float(hs[q]);
                if (v0 < thr) {
                    const int p = atomicAdd(&scnt[w], 1);
                    if (p < CAND_CAP) g_cand[(size_t)row * CAND_CAP + p] = i * 8 + q * 2;
                }
                if (v1 < thr) {
                    const int p = atomicAdd(&scnt[w], 1);
                    if (p < CAND_CAP) g_cand[(size_t)row * CAND_CAP + p] = i * 8 + q * 2 + 1;
                }
            }
        }
    }
    __syncwarp();

    if (lane == 0) {
        const int total = scnt[w];
        g_ccnt[row] = total;
        if (total > CAND_CAP) {
            const int p = atomicAdd(&g_wlf_count, 1);
            if (p < WLF_CAP) g_wlf[p] = row;
        } else if (total >= 2) {
            const int p = atomicAdd(&g_wlc_count, 1);
            if (p < WLC_CAP) g_wlc[p] = row;
        } else {
            g_argmin[row] = g_cand[(size_t)row * CAND_CAP];  // sole candidate
        }
    }
}

// ---------------------------------------------------------------------------
// refine_cand: exact fp64 rescore of tracked candidates. One warp per row.
// ---------------------------------------------------------------------------
__global__ __launch_bounds__(256)
void vq_refine_cand(const float* __restrict__ z) {
    const int cnt  = min(g_wlc_count, WLC_CAP);
    const int lane = threadIdx.x & 31;
    const int wrp  = threadIdx.x >> 5;

    for (int wi = blockIdx.x * 8 + wrp; wi < cnt; wi += gridDim.x * 8) {
        const int row = g_wlc[wi];
        const int nc = min(g_ccnt[row], CAND_CAP);
        const float* zr = z + (size_t)row * DIM;

        double bestV = 1e300;
        int    bestI = 0x7FFFFFFF;
        for (int j = 0; j < nc; j++) {
            const int k = g_cand[(size_t)row * CAND_CAP + j];
            const float* cw = g_cbT + (size_t)k * DIM;
            double sd = 0.0;
#pragma unroll 4
            for (int d = lane; d < DIM; d += 32)
                sd += (double)cw[d] * (double)zr[d];
#pragma unroll
            for (int off = 16; off > 0; off >>= 1)
                sd += __shfl_down_sync(0xFFFFFFFFu, sd, off);
            sd = __shfl_sync(0xFFFFFFFFu, sd, 0);
            if (sd < bestV || (sd == bestV && k < bestI)) { bestV = sd; bestI = k; }
        }
        if (lane == 0) g_argmin[row] = bestI;
    }
}

// ---------------------------------------------------------------------------
// refine_full: exact pass (fp32 full rescan -> fp64 finish) for overflow rows.
// ---------------------------------------------------------------------------
__global__ __launch_bounds__(256)
void vq_refine_full(const float* __restrict__ A) {
    __shared__ float  zs[DIM];
    __shared__ float  dots[KCB];
    __shared__ float  red[256];
    __shared__ int    cands[MAX_CAND];
    __shared__ double cval[MAX_CAND];
    __shared__ int    ncand;

    const int tid  = threadIdx.x;
    const int lane = tid & 31;
    const int wrp  = tid >> 5;
    const int cnt  = min(g_wlf_count, WLF_CAP);

    for (int wi = blockIdx.x; wi < cnt; wi += gridDim.x) {
        const int row = g_wlf[wi];
#pragma unroll
        for (int i = 0; i < DIM / 256; i++)
            zs[tid + i * 256] = A[(size_t)row * DIM + tid + i * 256];
        if (tid == 0) ncand = 0;
        __syncthreads();

        const float4* z4 = (const float4*)zs;
        float localMin = FLT_MAX;
        for (int k = tid; k < KCB; k += 256) {
            const float4* c4 = (const float4*)(g_cbT + (size_t)k * DIM);
            float sacc = 0.0f;
#pragma unroll 8
            for (int d = 0; d < DIM / 4; d++) {
                const float4 cc = c4[d];
                const float4 zz = z4[d];
                sacc = fmaf(cc.x, zz.x, sacc);
                sacc = fmaf(cc.y, zz.y, sacc);
                sacc = fmaf(cc.z, zz.z, sacc);
                sacc = fmaf(cc.w, zz.w, sacc);
            }
            dots[k] = sacc;
            localMin = fminf(localMin, sacc);
        }
        red[tid] = localMin;
        __syncthreads();
        for (int off = 128; off > 0; off >>= 1) {
            if (tid < off) red[tid] = fminf(red[tid], red[tid + off]);
            __syncthreads();
        }
        const float bmin = red[0];

        for (int k = tid; k < KCB; k += 256) {
            if (dots[k] < bmin + TAU3) {
                const int p = atomicAdd(&ncand, 1);
                if (p < MAX_CAND) cands[p] = k;
            }
        }
        __syncthreads();
        const int nc = min(ncand, MAX_CAND);

        for (int ci = wrp; ci < nc; ci += 8) {
            const int k = cands[ci];
            const float* cbp = g_cbT + (size_t)k * DIM;
            double sd = 0.0;
            for (int d = lane; d < DIM; d += 32)
                sd += (double)cbp[d] * (double)zs[d];
#pragma unroll
            for (int off = 16; off > 0; off >>= 1)
                sd += __shfl_down_sync(0xFFFFFFFFu, sd, off);
            if (lane == 0) cval[ci] = sd;
        }
        __syncthreads();

        if (tid == 0) {
            double bv = cval[0];
            int    bi = cands[0];
            for (int c2 = 1; c2 < nc; c2++) {
                const double v = cval[c2];
                const int    x = cands[c2];
                if (v < bv || (v == bv && x < bi)) { bv = v; bi = x; }
            }
            g_argmin[row] = bi;
        }
        __syncthreads();
    }
}

// ---------------------------------------------------------------------------
// Gather: out[n][:] = g_cbT[argmin[n]][:]
// ---------------------------------------------------------------------------
__global__ void vq_gather_kernel(float* __restrict__ out) {
    const int n = blockIdx.x;
    const int idx = g_argmin[n];
    const float4* src = (const float4*)(g_cbT + (size_t)idx * DIM);
    float4* dst = (float4*)(out + (size_t)n * DIM);
    dst[threadIdx.x] = src[threadIdx.x];
}

// ---------------------------------------------------------------------------
extern "C" void kernel_launch(void* const* d_in, const int* in_sizes, int n_in,
                              void* d_out, int out_size) {
    const float* z  = (const float*)d_in[0];
    const float* cb = (const float*)d_in[1];
    float* out = (float*)d_out;

    cudaFuncSetAttribute(vq_hmma1_kernel, cudaFuncAttributeMaxDynamicSharedMemorySize, H1_SMEM);

    dim3 tgrid(KCB / 32, DIM / 32);
    dim3 tblk(32, 8);
    vq_prep_cb<<<tgrid, tblk>>>(cb);
    vq_prep_z<<<8192, 256>>>(z);

    vq_hmma1_kernel<<<N_ROWS / BM, GEMM_THREADS, H1_SMEM>>>();

    vq_scan_kernel<<<N_ROWS / 8, 256>>>();
    vq_refine_cand<<<2048, 256>>>(z);
    vq_refine_full<<<64, 256>>>(z);
    vq_gather_kernel<<<N_ROWS, 256>>>(out);
}